// round 1
// baseline (speedup 1.0000x reference)
#include <cuda_runtime.h>
#include <cuda_bf16.h>
#include <math.h>

// ---------------- problem constants ----------------
#define BB    32
#define LL    1024
#define CIN   32
#define DM    512
#define NMARK 4
#define GG    4
#define DG    128
#define DIN   256
#define NST   16
#define DTR   8
#define PATCH 16
#define PRED  96
#define NTOK  (BB*PRED)      // 3072 tokens we actually need
#define NEXT  98             // per-batch extended token set for scale: l=0 and l=927..1023
#define LN1E4 9.210340371976184f

// ---------------- scratch (static __device__, no allocs) ----------------
__device__ float d_mean [BB*CIN];
__device__ float d_std  [BB*CIN];
__device__ float d_We   [100*DM];              // fused conv taps + temporal embed
__device__ float d_scale[BB*NEXT*CIN];
__device__ float d_xc   [NTOK*DM];             // e1+e2
__device__ float d_xz   [NTOK*2048];           // per-group in_proj output (xc|z)
__device__ float d_xconv[GG*NTOK*DIN];         // silu(depthwise conv)
__device__ float d_dbl  [GG*NTOK*40];          // x_proj output (dt_raw|B|C)
__device__ float d_dt   [GG*NTOK*DIN];         // softplus(dt)
__device__ float d_y    [GG*NTOK*DIN];         // scan output * silu(z)
__device__ float d_xm   [NTOK*DM];             // out_proj output

// ---------------- 1: per-(b,c) mean/std over L ----------------
__global__ void stats_kernel(const float* __restrict__ x_enc) {
    int bc = blockIdx.x;                       // b*32 + c
    const float* xp = x_enc + (size_t)(bc >> 5) * (LL*CIN) + (bc & 31);
    float s = 0.f, sq = 0.f;
    for (int l = threadIdx.x; l < LL; l += 256) {
        float v = xp[(size_t)l * CIN];
        s += v; sq += v * v;
    }
    __shared__ float sh[512];
    sh[threadIdx.x] = s; sh[256 + threadIdx.x] = sq;
    __syncthreads();
    for (int st = 128; st; st >>= 1) {
        if (threadIdx.x < st) {
            sh[threadIdx.x]       += sh[threadIdx.x + st];
            sh[256 + threadIdx.x] += sh[256 + threadIdx.x + st];
        }
        __syncthreads();
    }
    if (threadIdx.x == 0) {
        float m   = sh[0]   * (1.f / LL);
        float var = sh[256] * (1.f / LL) - m * m;
        d_mean[bc] = m;
        d_std[bc]  = sqrtf(var + 1e-5f);
    }
}

// ---------------- 2: build fused embed weight We[100][512] ----------------
// rows 0..95: tap k = r/32, channel c = r%32  ->  conv_w[d][c][k]
// rows 96..99: temporal mark m               ->  temp_w[d][m]
__global__ void prep_we_kernel(const float* __restrict__ conv_w,
                               const float* __restrict__ temp_w) {
    int idx = blockIdx.x * blockDim.x + threadIdx.x;
    if (idx >= 100 * DM) return;
    int r = idx / DM, d = idx % DM;
    float v;
    if (r < 96) {
        int k = r >> 5, c = r & 31;
        v = conv_w[d * 96 + c * 3 + k];
    } else {
        v = temp_w[d * 4 + (r - 96)];
    }
    d_We[idx] = v;
}

__device__ __forceinline__ float pe_val(int l, int d) {
    int i = d >> 1;
    float freq = expf(-(float)(2 * i) * (LN1E4 / (float)DM));
    float arg  = (float)l * freq;
    return (d & 1) ? cosf(arg) : sinf(arg);
}

// ---------------- 3: e1 for extended tokens + hetero scale ----------------
// grid: BB*NEXT blocks, 256 threads
__global__ void embed_scale_kernel(const float* __restrict__ x_enc,
                                   const float* __restrict__ mark,
                                   const float* __restrict__ hw,
                                   const float* __restrict__ hb) {
    int u = blockIdx.x % NEXT;
    int b = blockIdx.x / NEXT;
    int l  = (u == 0) ? 0 : (926 + u);         // 0 or 927..1023
    int lp = (l == 0) ? (LL - 1) : (l - 1);
    int ln = (l == LL - 1) ? 0 : (l + 1);

    __shared__ float inv[100];
    __shared__ float e1[DM];
    int tid = threadIdx.x;
    if (tid < 96) {
        int k = tid >> 5, c = tid & 31;
        int ll = (k == 0) ? lp : ((k == 1) ? l : ln);
        float v = x_enc[((size_t)b * LL + ll) * CIN + c];
        inv[tid] = (v - d_mean[b * CIN + c]) / d_std[b * CIN + c];
    } else if (tid < 100) {
        inv[tid] = mark[((size_t)b * LL + l) * NMARK + (tid - 96)];
    }
    __syncthreads();

    #pragma unroll
    for (int dd = 0; dd < 2; dd++) {
        int d = tid + dd * 256;
        float acc = 0.f;
        #pragma unroll 4
        for (int k = 0; k < 100; k++) acc += inv[k] * d_We[k * DM + d];
        e1[d] = acc + pe_val(l, d);
    }
    __syncthreads();

    int warp = tid >> 5, lane = tid & 31;
    #pragma unroll
    for (int ci = 0; ci < 4; ci++) {
        int c = warp * 4 + ci;
        float acc = 0.f;
        for (int d = lane; d < DM; d += 32) acc += e1[d] * hw[c * DM + d];
        #pragma unroll
        for (int o = 16; o; o >>= 1) acc += __shfl_down_sync(0xffffffffu, acc, o);
        if (lane == 0)
            d_scale[((size_t)b * NEXT + u) * CIN + c] = expf(acc + hb[c]);
    }
}

// ---------------- 4: xc = conv(x*(1+scale)) + 2*(mark term + pe) ----------------
// grid: NTOK blocks, 256 threads
__global__ void xc_kernel(const float* __restrict__ x_enc,
                          const float* __restrict__ mark) {
    int tok = blockIdx.x;
    int b = tok / PRED, j = tok % PRED;
    int l  = 928 + j;
    int lp = l - 1;                            // 927..1022
    int ln = (l == LL - 1) ? 0 : (l + 1);      // 929..1023 or 0

    __shared__ float inv[100];
    int tid = threadIdx.x;
    if (tid < 96) {
        int k = tid >> 5, c = tid & 31;
        int ll = (k == 0) ? lp : ((k == 1) ? l : ln);
        int u  = (ll == 0) ? 0 : (ll - 926);
        float v  = x_enc[((size_t)b * LL + ll) * CIN + c];
        float xn = (v - d_mean[b * CIN + c]) / d_std[b * CIN + c];
        inv[tid] = xn * (1.0f + d_scale[((size_t)b * NEXT + u) * CIN + c]);
    } else if (tid < 100) {
        inv[tid] = 2.0f * mark[((size_t)b * LL + l) * NMARK + (tid - 96)];
    }
    __syncthreads();

    #pragma unroll
    for (int dd = 0; dd < 2; dd++) {
        int d = tid + dd * 256;
        float acc = 0.f;
        #pragma unroll 4
        for (int k = 0; k < 100; k++) acc += inv[k] * d_We[k * DM + d];
        d_xc[(size_t)tok * DM + d] = acc + 2.0f * pe_val(l, d);
    }
}

// ---------------- generic tiled GEMM: C[M,N] = A[M,K] * W[N,K]^T ----------------
__global__ void __launch_bounds__(256)
gemm_tn(const float* __restrict__ A, const float* __restrict__ W,
        float* __restrict__ C, int M, int N, int K,
        int lda, int ldw, int ldc) {
    __shared__ float As[16][65];
    __shared__ float Ws[16][65];
    const int tid = threadIdx.x;
    const int tx = tid & 15, ty = tid >> 4;
    const int m0 = blockIdx.y * 64, n0 = blockIdx.x * 64;
    float acc[4][4] = {};
    const int lrow = tid >> 2;       // 0..63
    const int lk4  = (tid & 3) * 4;  // 0,4,8,12

    for (int k0 = 0; k0 < K; k0 += 16) {
        {
            int m = m0 + lrow;
            int n = n0 + lrow;
            #pragma unroll
            for (int i = 0; i < 4; i++) {
                int k = k0 + lk4 + i;
                As[lk4 + i][lrow] = (m < M && k < K) ? A[(size_t)m * lda + k] : 0.f;
                Ws[lk4 + i][lrow] = (n < N && k < K) ? W[(size_t)n * ldw + k] : 0.f;
            }
        }
        __syncthreads();
        #pragma unroll
        for (int kk = 0; kk < 16; kk++) {
            float a[4], w[4];
            #pragma unroll
            for (int i = 0; i < 4; i++) a[i] = As[kk][ty * 4 + i];
            #pragma unroll
            for (int j = 0; j < 4; j++) w[j] = Ws[kk][tx * 4 + j];
            #pragma unroll
            for (int i = 0; i < 4; i++)
                #pragma unroll
                for (int j = 0; j < 4; j++)
                    acc[i][j] += a[i] * w[j];
        }
        __syncthreads();
    }
    #pragma unroll
    for (int i = 0; i < 4; i++) {
        int m = m0 + ty * 4 + i;
        if (m >= M) continue;
        #pragma unroll
        for (int j = 0; j < 4; j++) {
            int n = n0 + tx * 4 + j;
            if (n < N) C[(size_t)m * ldc + n] = acc[i][j];
        }
    }
}

// ---------------- 5: depthwise causal conv (within patch) + SiLU ----------------
__global__ void conv_silu_kernel(const float* __restrict__ cw,
                                 const float* __restrict__ cb) {
    int idx = blockIdx.x * blockDim.x + threadIdx.x;   // g*NTOK*DIN + tok*DIN + e
    if (idx >= GG * NTOK * DIN) return;
    int e   = idx & (DIN - 1);
    int tmp = idx >> 8;
    int tok = tmp % NTOK;
    int g   = tmp / NTOK;
    int t    = tok & (PATCH - 1);
    int tok0 = tok - t;
    const float* base = d_xz + (size_t)tok0 * 2048 + g * 512 + e;
    float acc = cb[g * DIN + e];
    #pragma unroll
    for (int k = 0; k < 4; k++) {
        int tt = t - 3 + k;
        if (tt >= 0) acc += base[(size_t)tt * 2048] * cw[(g * DIN + e) * 4 + k];
    }
    float sig = 1.0f / (1.0f + expf(-acc));
    d_xconv[idx] = acc * sig;
}

// ---------------- 6: dt = softplus(dt_raw @ dt_w^T + dt_b) ----------------
__global__ void dt_kernel(const float* __restrict__ dtw,
                          const float* __restrict__ dtb) {
    int idx = blockIdx.x * blockDim.x + threadIdx.x;
    if (idx >= GG * NTOK * DIN) return;
    int e   = idx & (DIN - 1);
    int tmp = idx >> 8;
    int tok = tmp % NTOK;
    int g   = tmp / NTOK;
    const float* r = d_dbl + ((size_t)g * NTOK + tok) * 40;
    float acc = dtb[g * DIN + e];
    #pragma unroll
    for (int rr = 0; rr < DTR; rr++) acc += r[rr] * dtw[(g * DIN + e) * DTR + rr];
    d_dt[idx] = (acc > 20.f) ? acc : log1pf(expf(acc));
}

// ---------------- 7: selective scan, block per (g, b, p), thread per channel ----
__global__ void __launch_bounds__(256)
scan_kernel(const float* __restrict__ A_log, const float* __restrict__ Dp) {
    int gid = blockIdx.x;
    int g   = gid / (BB * 6);
    int row = gid % (BB * 6);
    int b = row / 6, p = row % 6;
    int tok0 = b * PRED + p * PATCH;
    int e = threadIdx.x;

    float Av[NST];
    #pragma unroll
    for (int n = 0; n < NST; n++) Av[n] = -expf(A_log[((size_t)g * DIN + e) * NST + n]);
    float Dv = Dp[g * DIN + e];
    float h[NST];
    #pragma unroll
    for (int n = 0; n < NST; n++) h[n] = 0.f;

    __shared__ float Bs[NST], Cs[NST];
    for (int t = 0; t < PATCH; t++) {
        int tok = tok0 + t;
        const float* dblrow = d_dbl + ((size_t)g * NTOK + tok) * 40;
        if (e < 16)       Bs[e]      = dblrow[8 + e];
        else if (e < 32)  Cs[e - 16] = dblrow[24 + (e - 16)];
        __syncthreads();

        size_t cidx = (size_t)g * NTOK * DIN + (size_t)tok * DIN + e;
        float dtv = d_dt[cidx];
        float xv  = d_xconv[cidx];
        float dx  = dtv * xv;
        float y = 0.f;
        #pragma unroll
        for (int n = 0; n < NST; n++) {
            h[n] = __expf(dtv * Av[n]) * h[n] + dx * Bs[n];
            y += h[n] * Cs[n];
        }
        y += Dv * xv;
        float zv = d_xz[(size_t)tok * 2048 + g * 512 + 256 + e];
        y *= zv / (1.0f + expf(-zv));
        d_y[cidx] = y;
        __syncthreads();
    }
}

// ---------------- 8: final projection + denorm + write output ----------------
__global__ void final_kernel(const float* __restrict__ ow, float* __restrict__ out) {
    int tok = blockIdx.x;
    int b = tok / PRED;
    __shared__ float xs[DM];
    int tid = threadIdx.x;
    xs[tid]       = d_xm[(size_t)tok * DM + tid];
    xs[tid + 256] = d_xm[(size_t)tok * DM + tid + 256];
    __syncthreads();
    int warp = tid >> 5, lane = tid & 31;
    #pragma unroll
    for (int ci = 0; ci < 4; ci++) {
        int c = warp * 4 + ci;
        float acc = 0.f;
        for (int d = lane; d < DM; d += 32) acc += xs[d] * ow[c * DM + d];
        #pragma unroll
        for (int o = 16; o; o >>= 1) acc += __shfl_down_sync(0xffffffffu, acc, o);
        if (lane == 0)
            out[(size_t)tok * CIN + c] = acc * d_std[b * CIN + c] + d_mean[b * CIN + c];
    }
}

// ---------------- host launcher ----------------
extern "C" void kernel_launch(void* const* d_in, const int* in_sizes, int n_in,
                              void* d_out, int out_size) {
    const float* x_enc     = (const float*)d_in[0];
    const float* x_mark    = (const float*)d_in[1];
    const float* conv_w    = (const float*)d_in[4];
    const float* temp_w    = (const float*)d_in[5];
    const float* hetero_w  = (const float*)d_in[6];
    const float* hetero_b  = (const float*)d_in[7];
    const float* in_proj_w = (const float*)d_in[8];
    const float* conv1_w   = (const float*)d_in[9];
    const float* conv1_b   = (const float*)d_in[10];
    const float* x_proj_w  = (const float*)d_in[11];
    const float* dt_proj_w = (const float*)d_in[12];
    const float* dt_proj_b = (const float*)d_in[13];
    const float* A_log     = (const float*)d_in[14];
    const float* D_param   = (const float*)d_in[15];
    const float* out_pw    = (const float*)d_in[16];
    const float* out_w     = (const float*)d_in[17];
    float* out = (float*)d_out;

    float *p_xc, *p_xz, *p_xconv, *p_dbl, *p_y, *p_xm;
    cudaGetSymbolAddress((void**)&p_xc,    d_xc);
    cudaGetSymbolAddress((void**)&p_xz,    d_xz);
    cudaGetSymbolAddress((void**)&p_xconv, d_xconv);
    cudaGetSymbolAddress((void**)&p_dbl,   d_dbl);
    cudaGetSymbolAddress((void**)&p_y,     d_y);
    cudaGetSymbolAddress((void**)&p_xm,    d_xm);

    stats_kernel<<<BB * CIN, 256>>>(x_enc);
    prep_we_kernel<<<(100 * DM + 255) / 256, 256>>>(conv_w, temp_w);
    embed_scale_kernel<<<BB * NEXT, 256>>>(x_enc, x_mark, hetero_w, hetero_b);
    xc_kernel<<<NTOK, 256>>>(x_enc, x_mark);

    // in_proj per group: (3072 x 128) @ (512 x 128)^T -> xz columns g*512..
    for (int g = 0; g < GG; g++) {
        gemm_tn<<<dim3(8, 48), 256>>>(p_xc + g * DG, in_proj_w + (size_t)g * 512 * DG,
                                      p_xz + g * 512, NTOK, 512, DG, DM, DG, 2048);
    }
    conv_silu_kernel<<<(GG * NTOK * DIN) / 256, 256>>>(conv1_w, conv1_b);

    // x_proj per group: (3072 x 256) @ (40 x 256)^T
    for (int g = 0; g < GG; g++) {
        gemm_tn<<<dim3(1, 48), 256>>>(p_xconv + (size_t)g * NTOK * DIN,
                                      x_proj_w + (size_t)g * 40 * DIN,
                                      p_dbl + (size_t)g * NTOK * 40,
                                      NTOK, 40, DIN, DIN, DIN, 40);
    }
    dt_kernel<<<(GG * NTOK * DIN) / 256, 256>>>(dt_proj_w, dt_proj_b);
    scan_kernel<<<GG * BB * 6, 256>>>(A_log, D_param);

    // out_proj per group: (3072 x 256) @ (128 x 256)^T -> xm columns g*128..
    for (int g = 0; g < GG; g++) {
        gemm_tn<<<dim3(2, 48), 256>>>(p_y + (size_t)g * NTOK * DIN,
                                      out_pw + (size_t)g * DG * DIN,
                                      p_xm + g * DG, NTOK, DG, DIN, DIN, DIN, DM);
    }
    final_kernel<<<NTOK, 256>>>(out_w, out);
}

// round 2
// speedup vs baseline: 1.7075x; 1.7075x over previous
#include <cuda_runtime.h>
#include <cuda_bf16.h>
#include <math.h>

// ---------------- problem constants ----------------
#define BB    32
#define LL    1024
#define CIN   32
#define DM    512
#define NMARK 4
#define GG    4
#define DG    128
#define DIN   256
#define NST   16
#define DTR   8
#define PATCH 16
#define PRED  96
#define NTOK  (BB*PRED)      // 3072 tokens actually needed
#define NEXT  98             // extended token set per batch: l=0 and l=927..1023
#define KE    112            // embed K padded to multiple of 16 (100 -> 112)
#define LN1E4 9.210340371976184f

// ---------------- scratch (static __device__, no allocs) ----------------
__device__ float d_mean [BB*CIN];
__device__ float d_std  [BB*CIN];
__device__ float d_We   [DM*KE];               // fused embed weight, [DM][KE] (cols 100..111 zero)
__device__ float d_pe   [NEXT*DM];             // positional embeds for the 98 needed l values
__device__ float d_A1   [BB*NEXT*KE];          // embed input rows for e1/scale
__device__ float d_e1   [BB*NEXT*DM];
__device__ float d_scale[BB*NEXT*CIN];
__device__ float d_A2   [NTOK*KE];             // embed input rows for xc
__device__ float d_xc   [NTOK*DM];
__device__ float d_xz   [NTOK*2048];           // in_proj output (per group: xc|z)
__device__ float d_xconv[GG*NTOK*DIN];         // silu(depthwise conv)
__device__ float d_dbl  [GG*NTOK*40];          // x_proj output (dt_raw|B|C)
__device__ float d_y    [GG*NTOK*DIN];         // scan output * silu(z)
__device__ float d_xm   [NTOK*DM];             // out_proj output

// ---------------- 1: per-(b,c) mean/std over L ----------------
__global__ void stats_kernel(const float* __restrict__ x_enc) {
    int bc = blockIdx.x;                       // b*32 + c
    const float* xp = x_enc + (size_t)(bc >> 5) * (LL*CIN) + (bc & 31);
    float s = 0.f, sq = 0.f;
    for (int l = threadIdx.x; l < LL; l += 256) {
        float v = xp[(size_t)l * CIN];
        s += v; sq += v * v;
    }
    __shared__ float sh[512];
    sh[threadIdx.x] = s; sh[256 + threadIdx.x] = sq;
    __syncthreads();
    for (int st = 128; st; st >>= 1) {
        if (threadIdx.x < st) {
            sh[threadIdx.x]       += sh[threadIdx.x + st];
            sh[256 + threadIdx.x] += sh[256 + threadIdx.x + st];
        }
        __syncthreads();
    }
    if (threadIdx.x == 0) {
        float m   = sh[0]   * (1.f / LL);
        float var = sh[256] * (1.f / LL) - m * m;
        d_mean[bc] = m;
        d_std[bc]  = sqrtf(var + 1e-5f);
    }
}

// ---------------- 2: build We^T ([DM][KE], zero-padded) + pe table (98x512) ---
__global__ void prep_kernel(const float* __restrict__ conv_w,
                            const float* __restrict__ temp_w) {
    int idx = blockIdx.x * blockDim.x + threadIdx.x;
    if (idx < DM * KE) {
        int d = idx / KE, r = idx % KE;
        float v = 0.f;
        if (r < 96)       v = conv_w[d * 96 + (r & 31) * 3 + (r >> 5)];
        else if (r < 100) v = temp_w[d * 4 + (r - 96)];
        d_We[idx] = v;                          // d_We[d][r]
    } else if (idx < DM * KE + NEXT * DM) {
        int j = idx - DM * KE;
        int u = j / DM, d = j % DM;
        int l = (u == 0) ? 0 : (926 + u);
        float freq = expf(-(float)(d & ~1) * (LN1E4 / (float)DM));
        float arg  = (float)l * freq;
        d_pe[j] = (d & 1) ? cosf(arg) : sinf(arg);
    }
}

// ---------------- 3a: build A1 rows (normalized window + mark) ----------------
__global__ void inv1_kernel(const float* __restrict__ x_enc,
                            const float* __restrict__ mark) {
    int row = blockIdx.x;                      // b*NEXT + u
    int tid = threadIdx.x;
    if (tid >= KE) return;
    int u = row % NEXT, b = row / NEXT;
    int l  = (u == 0) ? 0 : (926 + u);
    int lp = (l == 0) ? (LL - 1) : (l - 1);
    int ln = (l == LL - 1) ? 0 : (l + 1);
    float v = 0.f;
    if (tid < 96) {
        int k = tid >> 5, c = tid & 31;
        int ll = (k == 0) ? lp : ((k == 1) ? l : ln);
        float x = x_enc[((size_t)b * LL + ll) * CIN + c];
        v = (x - d_mean[b * CIN + c]) / d_std[b * CIN + c];
    } else if (tid < 100) {
        v = mark[((size_t)b * LL + l) * NMARK + (tid - 96)];
    }
    d_A1[(size_t)row * KE + tid] = v;
}

// ---------------- 3b: build A2 rows (normalized*(1+scale) + 2*mark) -----------
__global__ void inv2_kernel(const float* __restrict__ x_enc,
                            const float* __restrict__ mark) {
    int row = blockIdx.x;                      // tok = b*96 + j
    int tid = threadIdx.x;
    if (tid >= KE) return;
    int b = row / PRED, j = row % PRED;
    int l  = 928 + j;
    int lp = l - 1;
    int ln = (l == LL - 1) ? 0 : (l + 1);
    float v = 0.f;
    if (tid < 96) {
        int k = tid >> 5, c = tid & 31;
        int ll = (k == 0) ? lp : ((k == 1) ? l : ln);
        int u  = (ll == 0) ? 0 : (ll - 926);
        float x  = x_enc[((size_t)b * LL + ll) * CIN + c];
        float xn = (x - d_mean[b * CIN + c]) / d_std[b * CIN + c];
        v = xn * (1.0f + d_scale[((size_t)b * NEXT + u) * CIN + c]);
    } else if (tid < 100) {
        v = 2.0f * mark[((size_t)b * LL + l) * NMARK + (tid - 96)];
    }
    d_A2[(size_t)row * KE + tid] = v;
}

// ---------------- tiled GEMM: C[M,N] = A[M,K] @ W[N,K]^T, fused epilogues -----
// Requirements: M % 64 == 0, K % 16 == 0, lda/ldw % 4 == 0.
// EPI: 0=none  1=+pe[row%NEXT]  2=+2*pe[row%96+2]  3=exp(acc+aux[n])
//      4=acc*std[b,n]+mean[b,n] with b=row/96
template<int EPI>
__global__ void __launch_bounds__(256)
gemm_tn(const float* __restrict__ A, const float* __restrict__ W,
        float* __restrict__ C, const float* __restrict__ aux,
        int M, int N, int K, int lda, int ldw, int ldc,
        long sA, long sW, long sC) {
    int g = blockIdx.z;
    A += (long)g * sA; W += (long)g * sW; C += (long)g * sC;
    __shared__ __align__(16) float As[16][68];
    __shared__ __align__(16) float Ws[16][68];
    const int tid = threadIdx.x;
    const int tx = tid & 15, ty = tid >> 4;
    const int m0 = blockIdx.y * 64, n0 = blockIdx.x * 64;
    const int lrow = tid >> 2, lk4 = (tid & 3) * 4;
    float acc[4][4] = {};
    const int mg = m0 + lrow, ng = n0 + lrow;
    const bool nok = ng < N;
    const float* Aptr = A + (size_t)mg * lda + lk4;
    const float* Wptr = W + (size_t)(nok ? ng : 0) * ldw + lk4;

    for (int k0 = 0; k0 < K; k0 += 16) {
        float4 av = *(const float4*)(Aptr + k0);
        float4 wv = nok ? *(const float4*)(Wptr + k0) : make_float4(0.f,0.f,0.f,0.f);
        As[lk4 + 0][lrow] = av.x; As[lk4 + 1][lrow] = av.y;
        As[lk4 + 2][lrow] = av.z; As[lk4 + 3][lrow] = av.w;
        Ws[lk4 + 0][lrow] = wv.x; Ws[lk4 + 1][lrow] = wv.y;
        Ws[lk4 + 2][lrow] = wv.z; Ws[lk4 + 3][lrow] = wv.w;
        __syncthreads();
        #pragma unroll
        for (int kk = 0; kk < 16; kk++) {
            float4 a = *(const float4*)&As[kk][ty * 4];
            float4 w = *(const float4*)&Ws[kk][tx * 4];
            float ar[4] = {a.x, a.y, a.z, a.w};
            float wr[4] = {w.x, w.y, w.z, w.w};
            #pragma unroll
            for (int i = 0; i < 4; i++)
                #pragma unroll
                for (int j = 0; j < 4; j++)
                    acc[i][j] += ar[i] * wr[j];
        }
        __syncthreads();
    }

    #pragma unroll
    for (int i = 0; i < 4; i++) {
        int m = m0 + ty * 4 + i;               // M % 64 == 0 -> always valid
        #pragma unroll
        for (int j = 0; j < 4; j++) {
            int n = n0 + tx * 4 + j;
            if (n >= N) continue;
            float v = acc[i][j];
            if (EPI == 1) v += d_pe[(m % NEXT) * DM + n];
            if (EPI == 2) v += 2.0f * d_pe[(m % PRED + 2) * DM + n];
            if (EPI == 3) v = expf(v + aux[n]);
            if (EPI == 4) {
                int b = m / PRED;
                v = v * d_std[b * CIN + n] + d_mean[b * CIN + n];
            }
            C[(size_t)m * ldc + n] = v;
        }
    }
}

// ---------------- 5: depthwise conv + SiLU, block per (g,b,p), reg history ----
__global__ void __launch_bounds__(256)
conv_silu_kernel(const float* __restrict__ cw, const float* __restrict__ cb) {
    int gid = blockIdx.x;
    int g   = gid / (BB * 6);
    int row = gid % (BB * 6);
    int tok0 = (row / 6) * PRED + (row % 6) * PATCH;
    int e = threadIdx.x;
    float w0 = cw[(g * DIN + e) * 4 + 0];
    float w1 = cw[(g * DIN + e) * 4 + 1];
    float w2 = cw[(g * DIN + e) * 4 + 2];
    float w3 = cw[(g * DIN + e) * 4 + 3];
    float bv = cb[g * DIN + e];
    float h0 = 0.f, h1 = 0.f, h2 = 0.f;
    const float* src = d_xz + (size_t)tok0 * 2048 + g * 512 + e;
    float* dst = d_xconv + (size_t)g * NTOK * DIN + (size_t)tok0 * DIN + e;
    #pragma unroll
    for (int t = 0; t < PATCH; t++) {
        float xv = src[(size_t)t * 2048];
        float acc = bv + w0 * h0 + w1 * h1 + w2 * h2 + w3 * xv;
        h0 = h1; h1 = h2; h2 = xv;
        float sig = 1.0f / (1.0f + expf(-acc));
        dst[(size_t)t * DIN] = acc * sig;
    }
}

// ---------------- 7: selective scan with fused dt, block per (g,b,p) ----------
__global__ void __launch_bounds__(256)
scan_kernel(const float* __restrict__ A_log, const float* __restrict__ Dp,
            const float* __restrict__ dtw, const float* __restrict__ dtb) {
    int gid = blockIdx.x;
    int g   = gid / (BB * 6);
    int row = gid % (BB * 6);
    int tok0 = (row / 6) * PRED + (row % 6) * PATCH;
    int e = threadIdx.x;

    float Av[NST];
    #pragma unroll
    for (int n = 0; n < NST; n++) Av[n] = -expf(A_log[((size_t)g * DIN + e) * NST + n]);
    float Dv = Dp[g * DIN + e];
    float dtbv = dtb[g * DIN + e];
    float4 dw0 = *(const float4*)(dtw + (size_t)(g * DIN + e) * DTR);
    float4 dw1 = *(const float4*)(dtw + (size_t)(g * DIN + e) * DTR + 4);
    float h[NST];
    #pragma unroll
    for (int n = 0; n < NST; n++) h[n] = 0.f;

    __shared__ float sh[40];
    for (int t = 0; t < PATCH; t++) {
        int tok = tok0 + t;
        if (e < 40) sh[e] = d_dbl[((size_t)g * NTOK + tok) * 40 + e];
        __syncthreads();

        float dtv = dtbv
            + sh[0]*dw0.x + sh[1]*dw0.y + sh[2]*dw0.z + sh[3]*dw0.w
            + sh[4]*dw1.x + sh[5]*dw1.y + sh[6]*dw1.z + sh[7]*dw1.w;
        dtv = (dtv > 20.f) ? dtv : log1pf(expf(dtv));

        size_t cidx = (size_t)g * NTOK * DIN + (size_t)tok * DIN + e;
        float xv = d_xconv[cidx];
        float dx = dtv * xv;
        float y = 0.f;
        #pragma unroll
        for (int n = 0; n < NST; n++) {
            h[n] = __expf(dtv * Av[n]) * h[n] + dx * sh[8 + n];
            y += h[n] * sh[24 + n];
        }
        y += Dv * xv;
        float zv = d_xz[(size_t)tok * 2048 + g * 512 + 256 + e];
        y *= zv / (1.0f + expf(-zv));
        d_y[cidx] = y;
        __syncthreads();
    }
}

// ---------------- host launcher ----------------
extern "C" void kernel_launch(void* const* d_in, const int* in_sizes, int n_in,
                              void* d_out, int out_size) {
    const float* x_enc     = (const float*)d_in[0];
    const float* x_mark    = (const float*)d_in[1];
    const float* conv_w    = (const float*)d_in[4];
    const float* temp_w    = (const float*)d_in[5];
    const float* hetero_w  = (const float*)d_in[6];
    const float* hetero_b  = (const float*)d_in[7];
    const float* in_proj_w = (const float*)d_in[8];
    const float* conv1_w   = (const float*)d_in[9];
    const float* conv1_b   = (const float*)d_in[10];
    const float* x_proj_w  = (const float*)d_in[11];
    const float* dt_proj_w = (const float*)d_in[12];
    const float* dt_proj_b = (const float*)d_in[13];
    const float* A_log     = (const float*)d_in[14];
    const float* D_param   = (const float*)d_in[15];
    const float* out_pw    = (const float*)d_in[16];
    const float* out_w     = (const float*)d_in[17];
    float* out = (float*)d_out;

    float *p_A1, *p_e1, *p_A2, *p_xc, *p_xz, *p_xconv, *p_dbl, *p_y, *p_xm, *p_scale, *p_We;
    cudaGetSymbolAddress((void**)&p_A1,    d_A1);
    cudaGetSymbolAddress((void**)&p_e1,    d_e1);
    cudaGetSymbolAddress((void**)&p_A2,    d_A2);
    cudaGetSymbolAddress((void**)&p_xc,    d_xc);
    cudaGetSymbolAddress((void**)&p_xz,    d_xz);
    cudaGetSymbolAddress((void**)&p_xconv, d_xconv);
    cudaGetSymbolAddress((void**)&p_dbl,   d_dbl);
    cudaGetSymbolAddress((void**)&p_y,     d_y);
    cudaGetSymbolAddress((void**)&p_xm,    d_xm);
    cudaGetSymbolAddress((void**)&p_scale, d_scale);
    cudaGetSymbolAddress((void**)&p_We,    d_We);

    stats_kernel<<<BB * CIN, 256>>>(x_enc);
    prep_kernel<<<((KE + NEXT) * DM + 255) / 256, 256>>>(conv_w, temp_w);
    inv1_kernel<<<BB * NEXT, 128>>>(x_enc, x_mark);
    // e1 = A1 @ We^T (+pe): M=3136, N=512, K=112
    gemm_tn<1><<<dim3(8, 49, 1), 256>>>(p_A1, p_We, p_e1, nullptr,
                                        BB*NEXT, DM, KE, KE, KE, DM, 0, 0, 0);
    // scale = exp(e1 @ hetero_w^T + hb): M=3136, N=32, K=512
    gemm_tn<3><<<dim3(1, 49, 1), 256>>>(p_e1, hetero_w, p_scale, hetero_b,
                                        BB*NEXT, CIN, DM, DM, DM, CIN, 0, 0, 0);
    inv2_kernel<<<NTOK, 128>>>(x_enc, x_mark);
    // xc = A2 @ We^T (+2*pe): M=3072, N=512, K=112
    gemm_tn<2><<<dim3(8, 48, 1), 256>>>(p_A2, p_We, p_xc, nullptr,
                                        NTOK, DM, KE, KE, KE, DM, 0, 0, 0);
    // in_proj batched: (3072 x 512) = (3072 x 128) @ (512 x 128)^T per group
    gemm_tn<0><<<dim3(8, 48, GG), 256>>>(p_xc, in_proj_w, p_xz, nullptr,
                                         NTOK, 512, DG, DM, DG, 2048,
                                         DG, (long)512 * DG, 512);
    conv_silu_kernel<<<GG * BB * 6, 256>>>(conv1_w, conv1_b);
    // x_proj batched: (3072 x 40) = (3072 x 256) @ (40 x 256)^T per group
    gemm_tn<0><<<dim3(1, 48, GG), 256>>>(p_xconv, x_proj_w, p_dbl, nullptr,
                                         NTOK, 40, DIN, DIN, DIN, 40,
                                         (long)NTOK * DIN, 40L * DIN, (long)NTOK * 40);
    scan_kernel<<<GG * BB * 6, 256>>>(A_log, D_param, dt_proj_w, dt_proj_b);
    // out_proj batched: (3072 x 128) = (3072 x 256) @ (128 x 256)^T per group
    gemm_tn<0><<<dim3(2, 48, GG), 256>>>(p_y, out_pw, p_xm, nullptr,
                                         NTOK, DG, DIN, DIN, DIN, DM,
                                         (long)NTOK * DIN, (long)DG * DIN, DG);
    // final: out = (xm @ out_w^T) * std + mean : M=3072, N=32, K=512
    gemm_tn<4><<<dim3(1, 48, 1), 256>>>(p_xm, out_w, out, nullptr,
                                        NTOK, CIN, DM, DM, DM, CIN, 0, 0, 0);
}